// round 9
// baseline (speedup 1.0000x reference)
#include <cuda_runtime.h>
#include <cuda_fp16.h>
#include <cstdint>

// ---------------------------------------------------------------------------
// GINE encoder. GEMMs: fp16 mma.m16n8k16 + ldmatrix + cp.async double buffer.
// CTA tile 128x320 (4Mx4N warps of 32x80): A read exactly once per GEMM.
// Feature dim padded 300 -> 320 (pad cols identically 0 everywhere).
// ---------------------------------------------------------------------------

#define D0      300
#define DP      320
#define NMAX    100000
#define EMAX    250000
#define GMAX    4096
#define NLAYER  5
#define BN_EPS  1e-5f

__device__ __half g_h16[(size_t)NMAX * DP];
__device__ __half g_t16[(size_t)NMAX * DP];
__device__ __half g_e16[(size_t)EMAX * DP];
__device__ __half g_x16[(size_t)EMAX * DP];
__device__ __half g_p16[(size_t)GMAX * DP];
__device__ __half g_w16[13 * DP * DP];
__device__ float  g_agg[(size_t)NMAX * DP];
__device__ float  g_pool[(size_t)GMAX * DP];
__device__ float  g_cnt[GMAX];
__device__ float  g_sum[DP];
__device__ float  g_sq [DP];
__device__ float  g_scale[DP];
__device__ float  g_shift[DP];

// ---------------------------------------------------------------------------
__device__ __forceinline__ uint2 pack4h(float a, float b, float c, float d) {
    __half2 h0 = __floats2half2_rn(a, b);
    __half2 h1 = __floats2half2_rn(c, d);
    uint2 u;
    u.x = *reinterpret_cast<uint32_t*>(&h0);
    u.y = *reinterpret_cast<uint32_t*>(&h1);
    return u;
}

__global__ void k_fill0(float4* p, int n4) {
    int i = blockIdx.x * blockDim.x + threadIdx.x;
    if (i < n4) p[i] = make_float4(0.f, 0.f, 0.f, 0.f);
}

// all 13 weight matrices -> fp16 [320 n][320 k], transposed + zero padded
__global__ void k_wcvt_all(const float* __restrict__ nW2, const float* __restrict__ eW2,
                           const float* __restrict__ mW1, const float* __restrict__ mW2,
                           const float* __restrict__ pW,  __half* __restrict__ out) {
    int idx = blockIdx.x * blockDim.x + threadIdx.x;
    if (idx >= 13 * DP * DP) return;
    int m = idx / (DP * DP);
    int r = idx - m * (DP * DP);
    int k = r / DP, n = r - (r / DP) * DP;
    const float* W;
    if (m == 0)       W = nW2;
    else if (m == 1)  W = eW2;
    else if (m < 7)   W = mW1 + (size_t)(m - 2) * D0 * D0;
    else if (m < 12)  W = mW2 + (size_t)(m - 7) * D0 * D0;
    else              W = pW;
    float v = (k < D0 && n < D0) ? W[k * D0 + n] : 0.f;
    out[(size_t)m * DP * DP + (size_t)n * DP + k] = __float2half_rn(v);
}

__global__ void k_node_hidden(const float* __restrict__ ch, const float* __restrict__ fc,
                              const float* __restrict__ W,  const float* __restrict__ b,
                              __half* __restrict__ out, int N) {
    int idx = blockIdx.x * blockDim.x + threadIdx.x;
    if (idx >= N * 80) return;
    int i = idx / 80;
    int c = (idx - i * 80) * 4;
    float a0 = ch[i], a1 = fc[i];
    float o[4];
#pragma unroll
    for (int j = 0; j < 4; j++) {
        int col = c + j;
        o[j] = (col < D0)
             ? fmaxf(fmaf(a0, W[col], fmaf(a1, W[D0 + col], b[col])), 0.f) : 0.f;
    }
    *(uint2*)(out + (size_t)i * DP + c) = pack4h(o[0], o[1], o[2], o[3]);
}

__global__ void k_edge_hidden(const float* __restrict__ ea,
                              const float* __restrict__ W, const float* __restrict__ b,
                              __half* __restrict__ out, int E) {
    int idx = blockIdx.x * blockDim.x + threadIdx.x;
    if (idx >= E * 80) return;
    int i = idx / 80;
    int c = (idx - i * 80) * 4;
    float a0 = ea[(size_t)i * 3 + 0];
    float a1 = ea[(size_t)i * 3 + 1];
    float a2 = ea[(size_t)i * 3 + 2];
    float o[4];
#pragma unroll
    for (int j = 0; j < 4; j++) {
        int col = c + j;
        o[j] = (col < D0)
             ? fmaxf(fmaf(a0, W[col], fmaf(a1, W[D0 + col], fmaf(a2, W[2 * D0 + col], b[col]))), 0.f) : 0.f;
    }
    *(uint2*)(out + (size_t)i * DP + c) = pack4h(o[0], o[1], o[2], o[3]);
}

// flat scatter: one thread per (edge, 16B chunk); 38 chunks cover cols 0..303
__global__ void k_scatter(const int* __restrict__ src, const int* __restrict__ dst, int total) {
    int idx = blockIdx.x * blockDim.x + threadIdx.x;
    if (idx >= total) return;
    int e = idx / 38;
    int c = idx - e * 38;
    int s = src[e], d = dst[e];
    uint4 hu = *(const uint4*)(g_h16 + (size_t)s * DP + 8 * c);
    uint4 eu = *(const uint4*)(g_e16 + (size_t)e * DP + 8 * c);
    const __half2* h2 = (const __half2*)&hu;
    const __half2* e2 = (const __half2*)&eu;
    float v[8];
#pragma unroll
    for (int j = 0; j < 4; j++) {
        float2 fh = __half22float2(h2[j]);
        float2 fe = __half22float2(e2[j]);
        v[2 * j]     = fmaxf(fh.x + fe.x, 0.f);
        v[2 * j + 1] = fmaxf(fh.y + fe.y, 0.f);
    }
    float* ap = g_agg + (size_t)d * DP + 8 * c;
    asm volatile("red.global.add.v4.f32 [%0], {%1,%2,%3,%4};"
                 :: "l"(ap), "f"(v[0]), "f"(v[1]), "f"(v[2]), "f"(v[3]) : "memory");
    asm volatile("red.global.add.v4.f32 [%0], {%1,%2,%3,%4};"
                 :: "l"(ap + 4), "f"(v[4]), "f"(v[5]), "f"(v[6]), "f"(v[7]) : "memory");
}

// BN prep; zeroes stats after reading
__global__ void k_bnprep(const float* __restrict__ gamma, const float* __restrict__ beta, float invN) {
    int j = threadIdx.x;
    float mu  = g_sum[j] * invN;
    float var = g_sq[j] * invN - mu * mu;
    float inv = rsqrtf(var + BN_EPS);
    float ga = (j < D0) ? gamma[j] : 0.f;
    float be = (j < D0) ? beta[j]  : 0.f;
    float sc = ga * inv;
    g_scale[j] = sc;
    g_shift[j] = be - mu * sc;
    g_sum[j] = 0.f;
    g_sq[j]  = 0.f;
}

// v = relu(bn(agg)). LAST=false: h16 = v, agg = v. LAST=true: RED v into pool.
template <bool LAST>
__global__ void k_bnapply(const int* __restrict__ batch, int N) {
    int idx = blockIdx.x * blockDim.x + threadIdx.x;
    if (idx >= N * 80) return;
    int i = idx / 80;
    int c = (idx - i * 80) * 4;
    size_t off = (size_t)i * DP + c;
    float4 v = *(const float4*)(g_agg + off);
    v.x = fmaxf(fmaf(v.x, g_scale[c + 0], g_shift[c + 0]), 0.f);
    v.y = fmaxf(fmaf(v.y, g_scale[c + 1], g_shift[c + 1]), 0.f);
    v.z = fmaxf(fmaf(v.z, g_scale[c + 2], g_shift[c + 2]), 0.f);
    v.w = fmaxf(fmaf(v.w, g_scale[c + 3], g_shift[c + 3]), 0.f);
    if (!LAST) {
        *(uint2*)(g_h16 + off) = pack4h(v.x, v.y, v.z, v.w);
        *(float4*)(g_agg + off) = v;
    } else {
        int g = batch[i];
        float* pp = g_pool + (size_t)g * DP + c;
        asm volatile("red.global.add.v4.f32 [%0], {%1,%2,%3,%4};"
                     :: "l"(pp), "f"(v.x), "f"(v.y), "f"(v.z), "f"(v.w) : "memory");
    }
}

__global__ void k_count(const int* __restrict__ batch, int N) {
    int i = blockIdx.x * blockDim.x + threadIdx.x;
    if (i < N) atomicAdd(&g_cnt[batch[i]], 1.f);
}

__global__ void k_scalepool(int G) {
    int idx = blockIdx.x * blockDim.x + threadIdx.x;
    if (idx >= G * 80) return;
    int i = idx / 80;
    int c = (idx - i * 80) * 4;
    float s = 1.f / fmaxf(g_cnt[i], 1.f);
    float4 v = *(const float4*)(g_pool + (size_t)i * DP + c);
    *(uint2*)(g_p16 + (size_t)i * DP + c) = pack4h(v.x * s, v.y * s, v.z * s, v.w * s);
}

// ---------------------------------------------------------------------------
// fp16 tensor-core GEMM, 2-stage pipeline, ldmatrix fragments.
// C = epi( A[M,320] @ Wt^T + bias ), Wt fp16 [320 n][320 k].
// Block 128x320, BK=32, 512 thr, 16 warps (4M x 4N), warp tile 32x80.
// Grid is 1-D over rows: A is loaded exactly once.
// A32: A fp32 via LDG+cvt+STS (reg buffer); else fp16 cp.async.
// EPI: 0 half out, 1 relu half out, 2 +emb gather (half C + fp32 Cb),
//      3 fp32 out + BN col stats (warp-reduced REDG), 4 fp32 out stride 300.
// ---------------------------------------------------------------------------
#define BM 128
#define BN 320
#define BK 32
#define A_HALFS (BM * 40)                  // 5120
#define B_HALFS (BN * 40)                  // 12800
#define STG_HALFS (A_HALFS + B_HALFS)      // 17920
#define SMEM_BYTES (2 * STG_HALFS * 2)     // 71680

__device__ __forceinline__ void cp16(uint32_t dst, const void* src, bool pred) {
    int sz = pred ? 16 : 0;
    asm volatile("cp.async.ca.shared.global [%0], [%1], 16, %2;"
                 :: "r"(dst), "l"(src), "r"(sz));
}

__device__ __forceinline__ void ldsm4(uint32_t* r, uint32_t addr) {
    asm volatile("ldmatrix.sync.aligned.m8n8.x4.shared.b16 {%0,%1,%2,%3}, [%4];"
                 : "=r"(r[0]), "=r"(r[1]), "=r"(r[2]), "=r"(r[3]) : "r"(addr));
}
__device__ __forceinline__ void mma16(float* c, const uint32_t* a, const uint32_t* b) {
    asm volatile("mma.sync.aligned.m16n8k16.row.col.f32.f16.f16.f32 "
                 "{%0,%1,%2,%3}, {%4,%5,%6,%7}, {%8,%9}, {%0,%1,%2,%3};"
                 : "+f"(c[0]), "+f"(c[1]), "+f"(c[2]), "+f"(c[3])
                 : "r"(a[0]), "r"(a[1]), "r"(a[2]), "r"(a[3]), "r"(b[0]), "r"(b[1]));
}

template <int EPI, bool A32>
__global__ __launch_bounds__(512, 1)
void k_gemm(const void* __restrict__ Av, const __half* __restrict__ Wt,
            const float* __restrict__ bias, void* __restrict__ Cv,
            float* __restrict__ Cb, int M,
            const int* __restrict__ zidx, const float* __restrict__ emb) {
    extern __shared__ __align__(16) char smraw[];
    uint32_t smbase = (uint32_t)__cvta_generic_to_shared(smraw);

    const int tid = threadIdx.x;
    const int lane = tid & 31;
    const int wid = tid >> 5;
    const int warp_m = wid & 3;        // 4 warps along M
    const int warp_n = wid >> 2;       // 4 warps along N (covers 320)
    const int grp = lane >> 2;
    const int tg  = lane & 3;
    const int row0 = blockIdx.x * BM;

    const __half* Ah = (const __half*)Av;
    const float*  Af = (const float*)Av;

    float acc[2][10][4];
#pragma unroll
    for (int i = 0; i < 2; i++)
#pragma unroll
        for (int j = 0; j < 10; j++)
#pragma unroll
            for (int k = 0; k < 4; k++) acc[i][j][k] = 0.f;

    const int a_r = tid >> 2;          // 0..127
    const int a_c = tid & 3;           // 8-half (16B) chunk

    float ra[8];
    auto ldgA = [&](int k0) {
        int grow = row0 + a_r;
        if (grow < M) {
            const float* s = Af + (size_t)grow * DP + k0 + a_c * 8;
            float4 u0 = *(const float4*)s;
            float4 u1 = *(const float4*)(s + 4);
            ra[0] = u0.x; ra[1] = u0.y; ra[2] = u0.z; ra[3] = u0.w;
            ra[4] = u1.x; ra[5] = u1.y; ra[6] = u1.z; ra[7] = u1.w;
        } else {
#pragma unroll
            for (int j = 0; j < 8; j++) ra[j] = 0.f;
        }
    };
    auto stsA = [&](int stage) {
        uint2 p0 = pack4h(ra[0], ra[1], ra[2], ra[3]);
        uint2 p1 = pack4h(ra[4], ra[5], ra[6], ra[7]);
        *(uint4*)(smraw + stage * (STG_HALFS * 2) + (a_r * 40 + a_c * 8) * 2) =
            make_uint4(p0.x, p0.y, p1.x, p1.y);
    };
    auto loadA_async = [&](int stage, int k0) {
        uint32_t as = smbase + stage * (STG_HALFS * 2);
        int grow = row0 + a_r;
        bool ok = grow < M;
        cp16(as + (a_r * 40 + a_c * 8) * 2,
             Ah + (size_t)(ok ? grow : 0) * DP + k0 + a_c * 8, ok);
    };
    auto loadB = [&](int stage, int k0) {
        uint32_t bs = smbase + stage * (STG_HALFS * 2) + A_HALFS * 2;
#pragma unroll
        for (int it = 0; it < 3; it++) {
            int id = tid + it * 512;
            if (id < 1280) {
                int r = id >> 2, c = id & 3;
                cp16(bs + (r * 40 + c * 8) * 2,
                     Wt + (size_t)r * DP + k0 + c * 8, true);
            }
        }
    };

    if (A32) ldgA(0); else loadA_async(0, 0);
    loadB(0, 0);
    asm volatile("cp.async.commit_group;");

    const int NK = DP / BK;  // 10
    for (int it = 0; it < NK; it++) {
        if (A32) stsA(it & 1);
        if (it + 1 < NK) {
            if (A32) ldgA((it + 1) * BK);
            else     loadA_async((it + 1) & 1, (it + 1) * BK);
            loadB((it + 1) & 1, (it + 1) * BK);
            asm volatile("cp.async.commit_group;");
            asm volatile("cp.async.wait_group 1;");
        } else {
            asm volatile("cp.async.wait_group 0;");
        }
        __syncthreads();

        uint32_t as = smbase + (it & 1) * (STG_HALFS * 2);
        uint32_t bs = as + A_HALFS * 2;
        const int jj = lane >> 3, rr = lane & 7;
#pragma unroll
        for (int ks = 0; ks < 2; ks++) {
            uint32_t a[2][4];
#pragma unroll
            for (int mt = 0; mt < 2; mt++) {
                int m = warp_m * 32 + mt * 16 + (jj & 1) * 8 + rr;
                int kh = ks * 16 + (jj >> 1) * 8;
                ldsm4(a[mt], as + (m * 40 + kh) * 2);
            }
#pragma unroll
            for (int p = 0; p < 5; p++) {
                int n = warp_n * 80 + p * 16 + (jj >> 1) * 8 + rr;
                int kh = ks * 16 + (jj & 1) * 8;
                uint32_t r4[4];
                ldsm4(r4, bs + (n * 40 + kh) * 2);
                mma16(acc[0][2 * p],     a[0], r4);
                mma16(acc[0][2 * p + 1], a[0], r4 + 2);
                mma16(acc[1][2 * p],     a[1], r4);
                mma16(acc[1][2 * p + 1], a[1], r4 + 2);
            }
        }
        __syncthreads();
    }

    // ---- epilogue ----
#pragma unroll
    for (int nt = 0; nt < 10; nt++) {
        int cc = warp_n * 80 + nt * 8 + 2 * tg;
        float b0 = 0.f, b1 = 0.f;
        if (cc < D0) { b0 = bias[cc]; b1 = bias[cc + 1]; }
        float s0 = 0.f, s1 = 0.f, q0 = 0.f, q1 = 0.f;
#pragma unroll
        for (int mt = 0; mt < 2; mt++) {
#pragma unroll
            for (int h = 0; h < 2; h++) {
                int r = row0 + warp_m * 32 + mt * 16 + grp + h * 8;
                if (r >= M) continue;
                float v0 = acc[mt][nt][h * 2 + 0] + b0;
                float v1 = acc[mt][nt][h * 2 + 1] + b1;
                if (EPI == 1) { v0 = fmaxf(v0, 0.f); v1 = fmaxf(v1, 0.f); }
                if (EPI == 2) {
                    if (cc < D0) {
                        int zi = zidx[r];
                        v0 += emb[(size_t)zi * D0 + cc];
                        v1 += emb[(size_t)zi * D0 + cc + 1];
                    }
                }
                if (EPI == 3) { s0 += v0; s1 += v1; q0 += v0 * v0; q1 += v1 * v1; }
                if (EPI == 0 || EPI == 1 || EPI == 2) {
                    __half2 hv = __floats2half2_rn(v0, v1);
                    *(uint32_t*)((__half*)Cv + (size_t)r * DP + cc) =
                        *reinterpret_cast<uint32_t*>(&hv);
                    if (EPI == 2)
                        *(float2*)(Cb + (size_t)r * DP + cc) = make_float2(v0, v1);
                } else if (EPI == 3) {
                    *(float2*)((float*)Cv + (size_t)r * DP + cc) = make_float2(v0, v1);
                } else {  // EPI 4
                    if (cc < D0)
                        *(float2*)((float*)Cv + (size_t)r * D0 + cc) = make_float2(v0, v1);
                }
            }
        }
        if (EPI == 3) {
#pragma unroll
            for (int o = 4; o < 32; o <<= 1) {
                s0 += __shfl_xor_sync(0xffffffffu, s0, o);
                s1 += __shfl_xor_sync(0xffffffffu, s1, o);
                q0 += __shfl_xor_sync(0xffffffffu, q0, o);
                q1 += __shfl_xor_sync(0xffffffffu, q1, o);
            }
            if (grp == 0) {
                atomicAdd(&g_sum[cc], s0);
                atomicAdd(&g_sum[cc + 1], s1);
                atomicAdd(&g_sq[cc], q0);
                atomicAdd(&g_sq[cc + 1], q1);
            }
        }
    }
}

static void gemm_launch(int epi, const void* A, const __half* Wt, const float* bias,
                        void* C, float* Cb, int M, const int* z, const float* emb) {
    dim3 grid((M + BM - 1) / BM);
    switch (epi) {
        case 0:
            cudaFuncSetAttribute(k_gemm<0, false>, cudaFuncAttributeMaxDynamicSharedMemorySize, SMEM_BYTES);
            k_gemm<0, false><<<grid, 512, SMEM_BYTES>>>(A, Wt, bias, C, Cb, M, z, emb); break;
        case 1:
            cudaFuncSetAttribute(k_gemm<1, true>, cudaFuncAttributeMaxDynamicSharedMemorySize, SMEM_BYTES);
            k_gemm<1, true ><<<grid, 512, SMEM_BYTES>>>(A, Wt, bias, C, Cb, M, z, emb); break;
        case 2:
            cudaFuncSetAttribute(k_gemm<2, false>, cudaFuncAttributeMaxDynamicSharedMemorySize, SMEM_BYTES);
            k_gemm<2, false><<<grid, 512, SMEM_BYTES>>>(A, Wt, bias, C, Cb, M, z, emb); break;
        case 3:
            cudaFuncSetAttribute(k_gemm<3, false>, cudaFuncAttributeMaxDynamicSharedMemorySize, SMEM_BYTES);
            k_gemm<3, false><<<grid, 512, SMEM_BYTES>>>(A, Wt, bias, C, Cb, M, z, emb); break;
        case 4:
            cudaFuncSetAttribute(k_gemm<4, false>, cudaFuncAttributeMaxDynamicSharedMemorySize, SMEM_BYTES);
            k_gemm<4, false><<<grid, 512, SMEM_BYTES>>>(A, Wt, bias, C, Cb, M, z, emb); break;
    }
}

// ---------------------------------------------------------------------------
extern "C" void kernel_launch(void* const* d_in, const int* in_sizes, int n_in,
                              void* d_out, int out_size) {
    const int*   z     = (const int*)d_in[0];
    const float* ch    = (const float*)d_in[1];
    const float* fc    = (const float*)d_in[2];
    const int*   ei    = (const int*)d_in[3];
    const float* ea    = (const float*)d_in[4];
    const int*   batch = (const int*)d_in[5];

    int o = (in_sizes[6] == 1) ? 7 : 6;
    const float* atom_emb = (const float*)d_in[o + 0];
    const float* nW1   = (const float*)d_in[o + 1];
    const float* nb1   = (const float*)d_in[o + 2];
    const float* nW2   = (const float*)d_in[o + 3];
    const float* nb2   = (const float*)d_in[o + 4];
    const float* eW1   = (const float*)d_in[o + 5];
    const float* eb1   = (const float*)d_in[o + 6];
    const float* eW2   = (const float*)d_in[o + 7];
    const float* eb2   = (const float*)d_in[o + 8];
    const float* mW1   = (const float*)d_in[o + 9];
    const float* mb1   = (const float*)d_in[o + 10];
    const float* mW2   = (const float*)d_in[o + 11];
    const float* mb2   = (const float*)d_in[o + 12];
    const float* gamma = (const float*)d_in[o + 13];
    const float* beta  = (const float*)d_in[o + 14];
    const float* pW    = (const float*)d_in[o + 15];
    const float* pb    = (const float*)d_in[o + 16];

    int N = in_sizes[0];
    int E = in_sizes[3] / 2;
    int G = out_size / D0;
    const int* src = ei;
    const int* dst = ei + E;

    __half *ph16, *pt16, *pe16, *px16, *pp16, *pw16;
    float *pagg, *ppool, *pcnt;
    cudaGetSymbolAddress((void**)&ph16, g_h16);
    cudaGetSymbolAddress((void**)&pt16, g_t16);
    cudaGetSymbolAddress((void**)&pe16, g_e16);
    cudaGetSymbolAddress((void**)&px16, g_x16);
    cudaGetSymbolAddress((void**)&pp16, g_p16);
    cudaGetSymbolAddress((void**)&pw16, g_w16);
    cudaGetSymbolAddress((void**)&pagg, g_agg);
    cudaGetSymbolAddress((void**)&ppool, g_pool);
    cudaGetSymbolAddress((void**)&pcnt, g_cnt);

    const size_t WSZ = (size_t)DP * DP;
    int n4 = N * 80;
    int e4 = E * 80;
    int escat = E * 38;
    int g4 = G * 80;

    k_wcvt_all<<<(13 * DP * DP + 255) / 256, 256>>>(nW2, eW2, mW1, mW2, pW, pw16);

    k_fill0<<<(g4 + 255) / 256, 256>>>((float4*)ppool, g4);
    k_fill0<<<(G / 4 + 255) / 256, 256>>>((float4*)pcnt, G / 4);
    k_count<<<(N + 255) / 256, 256>>>(batch, N);

    // node encoder: h16 = atom_emb[z] + relu(attr@nW1+nb1)@nW2 + nb2; agg = h fp32
    k_node_hidden<<<(n4 + 255) / 256, 256>>>(ch, fc, nW1, nb1, px16, N);
    gemm_launch(2, px16, pw16 + 0 * WSZ, nb2, ph16, pagg, N, z, atom_emb);

    // edge encoder: e16 = relu(edge_attr@eW1+eb1)@eW2 + eb2
    k_edge_hidden<<<(e4 + 255) / 256, 256>>>(ea, eW1, eb1, px16, E);
    gemm_launch(0, px16, pw16 + 1 * WSZ, eb2, pe16, nullptr, E, nullptr, nullptr);

    for (int l = 0; l < NLAYER; l++) {
        k_scatter<<<(escat + 255) / 256, 256>>>(src, dst, escat);
        gemm_launch(1, pagg, pw16 + (2 + l) * WSZ, mb1 + (size_t)l * D0,
                    pt16, nullptr, N, nullptr, nullptr);
        gemm_launch(3, pt16, pw16 + (7 + l) * WSZ, mb2 + (size_t)l * D0,
                    pagg, nullptr, N, nullptr, nullptr);
        k_bnprep<<<1, DP>>>(gamma + (size_t)l * D0, beta + (size_t)l * D0, 1.f / (float)N);
        if (l + 1 < NLAYER)
            k_bnapply<false><<<(n4 + 255) / 256, 256>>>(nullptr, N);
        else
            k_bnapply<true><<<(n4 + 255) / 256, 256>>>(batch, N);
    }

    k_scalepool<<<(g4 + 255) / 256, 256>>>(G);
    gemm_launch(4, pp16, pw16 + 12 * WSZ, pb, d_out, nullptr, G, nullptr, nullptr);
}

// round 10
// speedup vs baseline: 1.0390x; 1.0390x over previous
#include <cuda_runtime.h>
#include <cuda_fp16.h>
#include <cstdint>

// ---------------------------------------------------------------------------
// GINE encoder. GEMMs: fp16 mma.m16n8k16 + ldmatrix + cp.async double buffer.
// Layer MLP fused: GEMM1 -> t in SMEM -> GEMM2 (one kernel, no global t).
// Other GEMMs: 128x160 tile, 2 CTA/SM (R8 best config).
// Feature dim padded 300 -> 320 (pad cols identically 0 everywhere).
// ---------------------------------------------------------------------------

#define D0      300
#define DP      320
#define NMAX    100000
#define EMAX    250000
#define GMAX    4096
#define NLAYER  5
#define BN_EPS  1e-5f

__device__ __half g_h16[(size_t)NMAX * DP];
__device__ __half g_e16[(size_t)EMAX * DP];
__device__ __half g_x16[(size_t)EMAX * DP];
__device__ __half g_p16[(size_t)GMAX * DP];
__device__ __half g_w16[13 * DP * DP];
__device__ float  g_agg[(size_t)NMAX * DP];
__device__ float  g_pool[(size_t)GMAX * DP];
__device__ float  g_cnt[GMAX];
__device__ float  g_sum[DP];
__device__ float  g_sq [DP];
__device__ float  g_scale[DP];
__device__ float  g_shift[DP];

// ---------------------------------------------------------------------------
__device__ __forceinline__ uint2 pack4h(float a, float b, float c, float d) {
    __half2 h0 = __floats2half2_rn(a, b);
    __half2 h1 = __floats2half2_rn(c, d);
    uint2 u;
    u.x = *reinterpret_cast<uint32_t*>(&h0);
    u.y = *reinterpret_cast<uint32_t*>(&h1);
    return u;
}

__global__ void k_fill0(float4* p, int n4) {
    int i = blockIdx.x * blockDim.x + threadIdx.x;
    if (i < n4) p[i] = make_float4(0.f, 0.f, 0.f, 0.f);
}

// all 13 weight matrices -> fp16 [320 n][320 k], transposed + zero padded
__global__ void k_wcvt_all(const float* __restrict__ nW2, const float* __restrict__ eW2,
                           const float* __restrict__ mW1, const float* __restrict__ mW2,
                           const float* __restrict__ pW,  __half* __restrict__ out) {
    int idx = blockIdx.x * blockDim.x + threadIdx.x;
    if (idx >= 13 * DP * DP) return;
    int m = idx / (DP * DP);
    int r = idx - m * (DP * DP);
    int k = r / DP, n = r - (r / DP) * DP;
    const float* W;
    if (m == 0)       W = nW2;
    else if (m == 1)  W = eW2;
    else if (m < 7)   W = mW1 + (size_t)(m - 2) * D0 * D0;
    else if (m < 12)  W = mW2 + (size_t)(m - 7) * D0 * D0;
    else              W = pW;
    float v = (k < D0 && n < D0) ? W[k * D0 + n] : 0.f;
    out[(size_t)m * DP * DP + (size_t)n * DP + k] = __float2half_rn(v);
}

__global__ void k_node_hidden(const float* __restrict__ ch, const float* __restrict__ fc,
                              const float* __restrict__ W,  const float* __restrict__ b,
                              __half* __restrict__ out, int N) {
    int idx = blockIdx.x * blockDim.x + threadIdx.x;
    if (idx >= N * 80) return;
    int i = idx / 80;
    int c = (idx - i * 80) * 4;
    float a0 = ch[i], a1 = fc[i];
    float o[4];
#pragma unroll
    for (int j = 0; j < 4; j++) {
        int col = c + j;
        o[j] = (col < D0)
             ? fmaxf(fmaf(a0, W[col], fmaf(a1, W[D0 + col], b[col])), 0.f) : 0.f;
    }
    *(uint2*)(out + (size_t)i * DP + c) = pack4h(o[0], o[1], o[2], o[3]);
}

__global__ void k_edge_hidden(const float* __restrict__ ea,
                              const float* __restrict__ W, const float* __restrict__ b,
                              __half* __restrict__ out, int E) {
    int idx = blockIdx.x * blockDim.x + threadIdx.x;
    if (idx >= E * 80) return;
    int i = idx / 80;
    int c = (idx - i * 80) * 4;
    float a0 = ea[(size_t)i * 3 + 0];
    float a1 = ea[(size_t)i * 3 + 1];
    float a2 = ea[(size_t)i * 3 + 2];
    float o[4];
#pragma unroll
    for (int j = 0; j < 4; j++) {
        int col = c + j;
        o[j] = (col < D0)
             ? fmaxf(fmaf(a0, W[col], fmaf(a1, W[D0 + col], fmaf(a2, W[2 * D0 + col], b[col]))), 0.f) : 0.f;
    }
    *(uint2*)(out + (size_t)i * DP + c) = pack4h(o[0], o[1], o[2], o[3]);
}

// flat scatter: one thread per (edge, 16B chunk); 38 chunks cover cols 0..303
__global__ void k_scatter(const int* __restrict__ src, const int* __restrict__ dst, int total) {
    int idx = blockIdx.x * blockDim.x + threadIdx.x;
    if (idx >= total) return;
    int e = idx / 38;
    int c = idx - e * 38;
    int s = src[e], d = dst[e];
    uint4 hu = *(const uint4*)(g_h16 + (size_t)s * DP + 8 * c);
    uint4 eu = *(const uint4*)(g_e16 + (size_t)e * DP + 8 * c);
    const __half2* h2 = (const __half2*)&hu;
    const __half2* e2 = (const __half2*)&eu;
    float v[8];
#pragma unroll
    for (int j = 0; j < 4; j++) {
        float2 fh = __half22float2(h2[j]);
        float2 fe = __half22float2(e2[j]);
        v[2 * j]     = fmaxf(fh.x + fe.x, 0.f);
        v[2 * j + 1] = fmaxf(fh.y + fe.y, 0.f);
    }
    float* ap = g_agg + (size_t)d * DP + 8 * c;
    asm volatile("red.global.add.v4.f32 [%0], {%1,%2,%3,%4};"
                 :: "l"(ap), "f"(v[0]), "f"(v[1]), "f"(v[2]), "f"(v[3]) : "memory");
    asm volatile("red.global.add.v4.f32 [%0], {%1,%2,%3,%4};"
                 :: "l"(ap + 4), "f"(v[4]), "f"(v[5]), "f"(v[6]), "f"(v[7]) : "memory");
}

// BN prep; zeroes stats after reading
__global__ void k_bnprep(const float* __restrict__ gamma, const float* __restrict__ beta, float invN) {
    int j = threadIdx.x;
    float mu  = g_sum[j] * invN;
    float var = g_sq[j] * invN - mu * mu;
    float inv = rsqrtf(var + BN_EPS);
    float ga = (j < D0) ? gamma[j] : 0.f;
    float be = (j < D0) ? beta[j]  : 0.f;
    float sc = ga * inv;
    g_scale[j] = sc;
    g_shift[j] = be - mu * sc;
    g_sum[j] = 0.f;
    g_sq[j]  = 0.f;
}

// v = relu(bn(agg)). LAST=false: h16 = v, agg = v. LAST=true: RED v into pool.
template <bool LAST>
__global__ void k_bnapply(const int* __restrict__ batch, int N) {
    int idx = blockIdx.x * blockDim.x + threadIdx.x;
    if (idx >= N * 80) return;
    int i = idx / 80;
    int c = (idx - i * 80) * 4;
    size_t off = (size_t)i * DP + c;
    float4 v = *(const float4*)(g_agg + off);
    v.x = fmaxf(fmaf(v.x, g_scale[c + 0], g_shift[c + 0]), 0.f);
    v.y = fmaxf(fmaf(v.y, g_scale[c + 1], g_shift[c + 1]), 0.f);
    v.z = fmaxf(fmaf(v.z, g_scale[c + 2], g_shift[c + 2]), 0.f);
    v.w = fmaxf(fmaf(v.w, g_scale[c + 3], g_shift[c + 3]), 0.f);
    if (!LAST) {
        *(uint2*)(g_h16 + off) = pack4h(v.x, v.y, v.z, v.w);
        *(float4*)(g_agg + off) = v;
    } else {
        int g = batch[i];
        float* pp = g_pool + (size_t)g * DP + c;
        asm volatile("red.global.add.v4.f32 [%0], {%1,%2,%3,%4};"
                     :: "l"(pp), "f"(v.x), "f"(v.y), "f"(v.z), "f"(v.w) : "memory");
    }
}

__global__ void k_count(const int* __restrict__ batch, int N) {
    int i = blockIdx.x * blockDim.x + threadIdx.x;
    if (i < N) atomicAdd(&g_cnt[batch[i]], 1.f);
}

__global__ void k_scalepool(int G) {
    int idx = blockIdx.x * blockDim.x + threadIdx.x;
    if (idx >= G * 80) return;
    int i = idx / 80;
    int c = (idx - i * 80) * 4;
    float s = 1.f / fmaxf(g_cnt[i], 1.f);
    float4 v = *(const float4*)(g_pool + (size_t)i * DP + c);
    *(uint2*)(g_p16 + (size_t)i * DP + c) = pack4h(v.x * s, v.y * s, v.z * s, v.w * s);
}

// ---------------------------------------------------------------------------
// shared GEMM primitives
// ---------------------------------------------------------------------------
__device__ __forceinline__ void cp16(uint32_t dst, const void* src, bool pred) {
    int sz = pred ? 16 : 0;
    asm volatile("cp.async.ca.shared.global [%0], [%1], 16, %2;"
                 :: "r"(dst), "l"(src), "r"(sz));
}
__device__ __forceinline__ void ldsm4(uint32_t* r, uint32_t addr) {
    asm volatile("ldmatrix.sync.aligned.m8n8.x4.shared.b16 {%0,%1,%2,%3}, [%4];"
                 : "=r"(r[0]), "=r"(r[1]), "=r"(r[2]), "=r"(r[3]) : "r"(addr));
}
__device__ __forceinline__ void mma16(float* c, const uint32_t* a, const uint32_t* b) {
    asm volatile("mma.sync.aligned.m16n8k16.row.col.f32.f16.f16.f32 "
                 "{%0,%1,%2,%3}, {%4,%5,%6,%7}, {%8,%9}, {%0,%1,%2,%3};"
                 : "+f"(c[0]), "+f"(c[1]), "+f"(c[2]), "+f"(c[3])
                 : "r"(a[0]), "r"(a[1]), "r"(a[2]), "r"(a[3]), "r"(b[0]), "r"(b[1]));
}

// ---------------------------------------------------------------------------
// Standalone GEMM (R8 config): block 128x160, 256 thr, 8 warps (4M x 2N),
// warp tile 32x80, 2 CTA/SM. A fp16.
// EPI: 0 half out, 2 +emb gather (half C + fp32 Cb), 4 fp32 out stride 300.
// ---------------------------------------------------------------------------
#define BM 128
#define BN 160
#define BK 32
#define A_HALFS (BM * 40)                  // 5120
#define B_HALFS (BN * 40)                  // 6400
#define STG_HALFS (A_HALFS + B_HALFS)      // 11520
#define SMEM_BYTES (2 * STG_HALFS * 2)     // 46080 < 48K

template <int EPI>
__global__ __launch_bounds__(256, 2)
void k_gemm(const __half* __restrict__ A, const __half* __restrict__ Wt,
            const float* __restrict__ bias, void* __restrict__ Cv,
            float* __restrict__ Cb, int M,
            const int* __restrict__ zidx, const float* __restrict__ emb) {
    extern __shared__ __align__(16) char smraw[];
    uint32_t smbase = (uint32_t)__cvta_generic_to_shared(smraw);

    const int tid = threadIdx.x;
    const int lane = tid & 31;
    const int wid = tid >> 5;
    const int warp_m = wid & 3;
    const int warp_n = wid >> 2;
    const int grp = lane >> 2;
    const int tg  = lane & 3;
    const int row0 = blockIdx.y * BM;
    const int col0 = blockIdx.x * BN;

    float acc[2][10][4];
#pragma unroll
    for (int i = 0; i < 2; i++)
#pragma unroll
        for (int j = 0; j < 10; j++)
#pragma unroll
            for (int k = 0; k < 4; k++) acc[i][j][k] = 0.f;

    const int a_r = tid >> 1;
    const int a_c = tid & 1;

    auto loadA = [&](int stage, int k0) {
        uint32_t as = smbase + stage * (STG_HALFS * 2);
        int grow = row0 + a_r;
        bool ok = grow < M;
        const __half* s = A + (size_t)(ok ? grow : 0) * DP + k0 + a_c * 16;
        cp16(as + (a_r * 40 + a_c * 16) * 2, s, ok);
        cp16(as + (a_r * 40 + a_c * 16 + 8) * 2, s + 8, ok);
    };
    auto loadB = [&](int stage, int k0) {
        uint32_t bs = smbase + stage * (STG_HALFS * 2) + A_HALFS * 2;
#pragma unroll
        for (int it = 0; it < 3; it++) {
            int id = tid + it * 256;
            if (id < 640) {
                int r = id >> 2, c = id & 3;
                cp16(bs + (r * 40 + c * 8) * 2,
                     Wt + (size_t)(col0 + r) * DP + k0 + c * 8, true);
            }
        }
    };

    loadA(0, 0);
    loadB(0, 0);
    asm volatile("cp.async.commit_group;");

    const int NK = DP / BK;  // 10
    for (int it = 0; it < NK; it++) {
        if (it + 1 < NK) {
            loadA((it + 1) & 1, (it + 1) * BK);
            loadB((it + 1) & 1, (it + 1) * BK);
            asm volatile("cp.async.commit_group;");
            asm volatile("cp.async.wait_group 1;");
        } else {
            asm volatile("cp.async.wait_group 0;");
        }
        __syncthreads();

        uint32_t as = smbase + (it & 1) * (STG_HALFS * 2);
        uint32_t bs = as + A_HALFS * 2;
        const int jj = lane >> 3, rr = lane & 7;
#pragma unroll
        for (int ks = 0; ks < 2; ks++) {
            uint32_t a[2][4];
#pragma unroll
            for (int mt = 0; mt < 2; mt++) {
                int m = warp_m * 32 + mt * 16 + (jj & 1) * 8 + rr;
                int kh = ks * 16 + (jj >> 1) * 8;
                ldsm4(a[mt], as + (m * 40 + kh) * 2);
            }
#pragma unroll
            for (int p = 0; p < 5; p++) {
                int n = warp_n * 80 + p * 16 + (jj >> 1) * 8 + rr;
                int kh = ks * 16 + (jj & 1) * 8;
                uint32_t r4[4];
                ldsm4(r4, bs + (n * 40 + kh) * 2);
                mma16(acc[0][2 * p],     a[0], r4);
                mma16(acc[0][2 * p + 1], a[0], r4 + 2);
                mma16(acc[1][2 * p],     a[1], r4);
                mma16(acc[1][2 * p + 1], a[1], r4 + 2);
            }
        }
        __syncthreads();
    }

#pragma unroll
    for (int nt = 0; nt < 10; nt++) {
        int cc = col0 + warp_n * 80 + nt * 8 + 2 * tg;
        float b0 = 0.f, b1 = 0.f;
        if (cc < D0) { b0 = bias[cc]; b1 = bias[cc + 1]; }
#pragma unroll
        for (int mt = 0; mt < 2; mt++) {
#pragma unroll
            for (int h = 0; h < 2; h++) {
                int r = row0 + warp_m * 32 + mt * 16 + grp + h * 8;
                if (r >= M) continue;
                float v0 = acc[mt][nt][h * 2 + 0] + b0;
                float v1 = acc[mt][nt][h * 2 + 1] + b1;
                if (EPI == 2) {
                    if (cc < D0) {
                        int zi = zidx[r];
                        v0 += emb[(size_t)zi * D0 + cc];
                        v1 += emb[(size_t)zi * D0 + cc + 1];
                    }
                }
                if (EPI == 0 || EPI == 2) {
                    __half2 hv = __floats2half2_rn(v0, v1);
                    *(uint32_t*)((__half*)Cv + (size_t)r * DP + cc) =
                        *reinterpret_cast<uint32_t*>(&hv);
                    if (EPI == 2)
                        *(float2*)(Cb + (size_t)r * DP + cc) = make_float2(v0, v1);
                } else {  // EPI 4
                    if (cc < D0)
                        *(float2*)((float*)Cv + (size_t)r * D0 + cc) = make_float2(v0, v1);
                }
            }
        }
    }
}

static void gemm_launch(int epi, const __half* A, const __half* Wt, const float* bias,
                        void* C, float* Cb, int M, const int* z, const float* emb) {
    dim3 grid(2, (M + BM - 1) / BM);
    switch (epi) {
        case 0: k_gemm<0><<<grid, 256, SMEM_BYTES>>>(A, Wt, bias, C, Cb, M, z, emb); break;
        case 2: k_gemm<2><<<grid, 256, SMEM_BYTES>>>(A, Wt, bias, C, Cb, M, z, emb); break;
        case 4: k_gemm<4><<<grid, 256, SMEM_BYTES>>>(A, Wt, bias, C, Cb, M, z, emb); break;
    }
}

// ---------------------------------------------------------------------------
// Fused layer MLP: agg_out = (relu(agg@W1+b1))@W2 + b2, with BN col stats.
// Block 128 rows x all 320 cols, 512 thr, 16 warps (4M x 4N), warp tile 32x80.
// Phase 1: A = agg fp32 (LDG+cvt+STS double-buffered), result t -> SMEM fp16.
// Phase 2: A-fragments ldmatrix'd straight out of the t buffer (no staging).
// ---------------------------------------------------------------------------
#define TSTR 328
#define T_HALFS (128 * TSTR)            // 41984
#define FA_HALFS (128 * 40)             // 5120
#define FB_HALFS (320 * 40)             // 12800
#define MLP_SMEM ((T_HALFS + 2 * FA_HALFS + 2 * FB_HALFS) * 2)  // 155648

__global__ __launch_bounds__(512, 1)
void k_mlp(const float* __restrict__ A, const __half* __restrict__ W1t,
           const float* __restrict__ b1v, const __half* __restrict__ W2t,
           const float* __restrict__ b2v, float* __restrict__ Cout, int M) {
    extern __shared__ __align__(16) char smraw[];
    uint32_t smbase = (uint32_t)__cvta_generic_to_shared(smraw);
    const uint32_t tb   = smbase;                                  // t buffer
    const uint32_t stA  = smbase + T_HALFS * 2;
    const uint32_t stB  = smbase + (T_HALFS + 2 * FA_HALFS) * 2;

    const int tid = threadIdx.x;
    const int lane = tid & 31;
    const int wid = tid >> 5;
    const int warp_m = wid & 3;
    const int warp_n = wid >> 2;
    const int grp = lane >> 2;
    const int tg  = lane & 3;
    const int row0 = blockIdx.x * 128;
    const int jj = lane >> 3, rr = lane & 7;

    float acc[2][10][4];
#pragma unroll
    for (int i = 0; i < 2; i++)
#pragma unroll
        for (int j = 0; j < 10; j++)
#pragma unroll
            for (int k = 0; k < 4; k++) acc[i][j][k] = 0.f;

    const int a_r = tid >> 2;
    const int a_c = tid & 3;

    float ra[8];
    auto ldgA = [&](int k0) {
        int grow = row0 + a_r;
        if (grow < M) {
            const float* s = A + (size_t)grow * DP + k0 + a_c * 8;
            float4 u0 = *(const float4*)s;
            float4 u1 = *(const float4*)(s + 4);
            ra[0] = u0.x; ra[1] = u0.y; ra[2] = u0.z; ra[3] = u0.w;
            ra[4] = u1.x; ra[5] = u1.y; ra[6] = u1.z; ra[7] = u1.w;
        } else {
#pragma unroll
            for (int j = 0; j < 8; j++) ra[j] = 0.f;
        }
    };
    auto stsA = [&](int stage) {
        uint2 p0 = pack4h(ra[0], ra[1], ra[2], ra[3]);
        uint2 p1 = pack4h(ra[4], ra[5], ra[6], ra[7]);
        *(uint4*)(smraw + (T_HALFS + stage * FA_HALFS + a_r * 40 + a_c * 8) * 2) =
            make_uint4(p0.x, p0.y, p1.x, p1.y);
    };
    auto loadB = [&](const __half* W, int stage, int k0) {
        uint32_t bs = stB + stage * (FB_HALFS * 2);
#pragma unroll
        for (int it = 0; it < 3; it++) {
            int id = tid + it * 512;
            if (id < 1280) {
                int r = id >> 2, c = id & 3;
                cp16(bs + (r * 40 + c * 8) * 2,
                     W + (size_t)r * DP + k0 + c * 8, true);
            }
        }
    };

    // ---------------- phase 1: t = relu(A @ W1 + b1) ----------------
    ldgA(0);
    loadB(W1t, 0, 0);
    asm volatile("cp.async.commit_group;");

    for (int it = 0; it < 10; it++) {
        stsA(it & 1);
        if (it + 1 < 10) {
            ldgA((it + 1) * BK);
            loadB(W1t, (it + 1) & 1, (it + 1) * BK);
            asm volatile("cp.async.commit_group;");
            asm volatile("cp.async.wait_group 1;");
        } else {
            asm volatile("cp.async.wait_group 0;");
        }
        __syncthreads();

        uint32_t as = stA + (it & 1) * (FA_HALFS * 2);
        uint32_t bs = stB + (it & 1) * (FB_HALFS * 2);
#pragma unroll
        for (int ks = 0; ks < 2; ks++) {
            uint32_t a[2][4];
#pragma unroll
            for (int mt = 0; mt < 2; mt++) {
                int m = warp_m * 32 + mt * 16 + (jj & 1) * 8 + rr;
                int kh = ks * 16 + (jj >> 1) * 8;
                ldsm4(a[mt], as + (m * 40 + kh) * 2);
            }
#pragma unroll
            for (int p = 0; p < 5; p++) {
                int n = warp_n * 80 + p * 16 + (jj >> 1) * 8 + rr;
                int kh = ks * 16 + (jj & 1) * 8;
                uint32_t r4[4];
                ldsm4(r4, bs + (n * 40 + kh) * 2);
                mma16(acc[0][2 * p],     a[0], r4);
                mma16(acc[0][2 * p + 1], a[0], r4 + 2);
                mma16(acc[1][2 * p],     a[1], r4);
                mma16(acc[1][2 * p + 1], a[1], r4 + 2);
            }
        }
        __syncthreads();
    }

    // prefetch W2 chunk 0 while epilogue runs
    loadB(W2t, 0, 0);
    asm volatile("cp.async.commit_group;");

    // epilogue 1: relu + bias -> t SMEM (fp16); reset acc
#pragma unroll
    for (int nt = 0; nt < 10; nt++) {
        int cc = warp_n * 80 + nt * 8 + 2 * tg;
        float b0 = 0.f, b1 = 0.f;
        if (cc < D0) { b0 = b1v[cc]; b1 = b1v[cc + 1]; }
#pragma unroll
        for (int mt = 0; mt < 2; mt++) {
#pragma unroll
            for (int h = 0; h < 2; h++) {
                int lr = warp_m * 32 + mt * 16 + grp + h * 8;
                float v0 = fmaxf(acc[mt][nt][h * 2 + 0] + b0, 0.f);
                float v1 = fmaxf(acc[mt][nt][h * 2 + 1] + b1, 0.f);
                __half2 hv = __floats2half2_rn(v0, v1);
                *(uint32_t*)(smraw + (lr * TSTR + cc) * 2) =
                    *reinterpret_cast<uint32_t*>(&hv);
                acc[mt][nt][h * 2 + 0] = 0.f;
                acc[mt][nt][h * 2 + 1] = 0.f;
            }
        }
    }
    __syncthreads();

    // ---------------- phase 2: out = t @ W2 + b2 (+ stats) ----------------
    for (int it = 0; it < 10; it++) {
        if (it + 1 < 10) {
            loadB(W2t, (it + 1) & 1, (it + 1) * BK);
            asm volatile("cp.async.commit_group;");
            asm volatile("cp.async.wait_group 1;");
        } else {
            asm volatile("cp.async.wait_group 0;");
        }
        __syncthreads();

        int k0 = it * BK;
        uint32_t bs = stB + (it & 1) * (FB_HALFS * 2);
#pragma unroll
        for (int ks = 0; ks < 2; ks++) {
            uint32_t a[2][4];
#pragma unroll
            for (int mt = 0; mt < 2; mt++) {
                int m = warp_m * 32 + mt * 16 + (jj & 1) * 8 + rr;
                int kh = k0 + ks * 16 + (jj >> 1) * 8;
                ldsm4(a[mt], tb + (m * TSTR + kh) * 2);
            }
#pragma unroll
            for (int p = 0; p < 5; p++) {
                int n = warp_n * 80 + p * 16 + (jj >> 1) * 8 + rr;
                int kh = ks * 16 + (jj & 1) * 8;
                uint32_t r4[4];
                ldsm4(r4, bs + (n * 40 + kh) * 2);
                mma16(acc[0][2 * p],     a[0], r4);
                mma16(acc[0][2 * p + 1], a[0], r4 + 2);
                mma16(acc[1][2 * p],     a[1], r4);
                mma16(acc[1][2 * p + 1], a[1], r4 + 2);
            }
        }
        __syncthreads();
    }

    // epilogue 2: fp32 out + BN column stats
#pragma unroll
    for (int nt = 0; nt < 10; nt++) {
        int cc = warp_n * 80 + nt * 8 + 2 * tg;
        float b0 = 0.f, b1 = 0.f;
        if (cc < D0) { b0 = b2v[cc]; b1 = b2v[cc + 1]; }
        float s0 = 0.f, s1 = 0.f, q0 = 0.f, q1 = 0.f;
#pragma unroll
        for (int mt = 0; mt < 2; mt++) {
#pragma unroll
            for (int h = 0; h < 2; h++) {
                int r = row0 + warp_m * 32 + mt * 16 + grp + h * 8;
                if (r >= M) continue;
                float v0 = acc[mt][nt][h * 2 + 0] + b0;
                float v1 = acc[mt][nt][h * 2 + 1] + b1;
                s0 += v0; s1 += v1; q0 += v0 * v0; q1 += v1 * v1;
                *(float2*)(Cout + (size_t)r * DP + cc) = make_float2(v0, v1);
            }
        }
#pragma unroll
        for (int o = 4; o < 32; o <<= 1) {
            s0 += __shfl_xor_sync(0xffffffffu, s0, o);
            s1 += __shfl_xor_sync(0xffffffffu, s1, o);
            q0 += __shfl_xor_sync(0xffffffffu, q0, o);
            q1 += __shfl_xor_sync(0xffffffffu, q1, o);
        }
        if (grp == 0) {
            atomicAdd(&g_sum[cc], s0);
            atomicAdd(&g_sum[cc + 1], s1);
            atomicAdd(&g_sq[cc], q0);
            atomicAdd(&g_sq[cc + 1], q1);
        }
    }
}

// ---------------------------------------------------------------------------
extern "C" void kernel_launch(void* const* d_in, const int* in_sizes, int n_in,
                              void* d_out, int out_size) {
    const int*   z     = (const int*)d_in[0];
    const float* ch    = (const float*)d_in[1];
    const float* fc    = (const float*)d_in[2];
    const int*   ei    = (const int*)d_in[3];
    const float* ea    = (const float*)d_in[4];
    const int*   batch = (const int*)d_in[5];

    int o = (in_sizes[6] == 1) ? 7 : 6;
    const float* atom_emb = (const float*)d_in[o + 0];
    const float* nW1   = (const float*)d_in[o + 1];
    const float* nb1   = (const float*)d_in[o + 2];
    const float* nW2   = (const float*)d_in[o + 3];
    const float* nb2   = (const float*)d_in[o + 4];
    const float* eW1   = (const float*)d_in[o + 5];
    const float* eb1   = (const float*)d_in[o + 6];
    const float* eW2   = (const float*)d_in[o + 7];
    const float* eb2   = (const float*)d_in[o + 8];
    const float* mW1   = (const float*)d_in[o + 9];
    const float* mb1   = (const float*)d_in[o + 10];
    const float* mW2   = (const float*)d_in[o + 11];
    const float* mb2   = (const float*)d_in[o + 12];
    const float* gamma = (const float*)d_in[o + 13];
    const float* beta  = (const float*)d_in[o + 14];
    const float* pW    = (const float*)d_in[o + 15];
    const float* pb    = (const float*)d_in[o + 16];

    int N = in_sizes[0];
    int E = in_sizes[3] / 2;
    int G = out_size / D0;
    const int* src = ei;
    const int* dst = ei + E;

    __half *ph16, *pe16, *px16, *pp16, *pw16;
    float *pagg, *ppool, *pcnt;
    cudaGetSymbolAddress((void**)&ph16, g_h16);
    cudaGetSymbolAddress((void**)&pe16, g_e16);
    cudaGetSymbolAddress((void**)&px16, g_x16);
    cudaGetSymbolAddress((void**)&pp16, g_p16);
    cudaGetSymbolAddress((void**)&pw16, g_w16);
    cudaGetSymbolAddress((void**)&pagg, g_agg);
    cudaGetSymbolAddress((void**)&ppool, g_pool);
    cudaGetSymbolAddress((void**)&pcnt, g_cnt);

    cudaFuncSetAttribute(k_mlp, cudaFuncAttributeMaxDynamicSharedMemorySize, MLP_SMEM);

    const size_t WSZ = (size_t)DP * DP;
    int n4 = N * 80;
    int e4 = E * 80;
    int escat = E * 38;
    int g4 = G * 80;

    k_wcvt_all<<<(13 * DP * DP + 255) / 256, 256>>>(nW2, eW2, mW1, mW2, pW, pw16);

    k_fill0<<<(g4 + 255) / 256, 256>>>((float4*)ppool, g4);
    k_fill0<<<(G / 4 + 255) / 256, 256>>>((float4*)pcnt, G / 4);
    k_count<<<(N + 255) / 256, 256>>>(batch, N);

    // node encoder: h16 = atom_emb[z] + relu(attr@nW1+nb1)@nW2 + nb2; agg = h fp32
    k_node_hidden<<<(n4 + 255) / 256, 256>>>(ch, fc, nW1, nb1, px16, N);
    gemm_launch(2, px16, pw16 + 0 * WSZ, nb2, ph16, pagg, N, z, atom_emb);

    // edge encoder: e16 = relu(edge_attr@eW1+eb1)@eW2 + eb2
    k_edge_hidden<<<(e4 + 255) / 256, 256>>>(ea, eW1, eb1, px16, E);
    gemm_launch(0, px16, pw16 + 1 * WSZ, eb2, pe16, nullptr, E, nullptr, nullptr);

    int mgrid = (N + 127) / 128;
    for (int l = 0; l < NLAYER; l++) {
        k_scatter<<<(escat + 255) / 256, 256>>>(src, dst, escat);
        // agg = mlp2(agg) with fused stats (t never leaves SMEM)
        k_mlp<<<mgrid, 512, MLP_SMEM>>>(pagg, pw16 + (2 + l) * WSZ, mb1 + (size_t)l * D0,
                                        pw16 + (7 + l) * WSZ, mb2 + (size_t)l * D0,
                                        pagg, N);
        k_bnprep<<<1, DP>>>(gamma + (size_t)l * D0, beta + (size_t)l * D0, 1.f / (float)N);
        if (l + 1 < NLAYER)
            k_bnapply<false><<<(n4 + 255) / 256, 256>>>(nullptr, N);
        else
            k_bnapply<true><<<(n4 + 255) / 256, 256>>>(batch, N);
    }

    k_scalepool<<<(g4 + 255) / 256, 256>>>(G);
    gemm_launch(4, pp16, pw16 + 12 * WSZ, pb, d_out, nullptr, G, nullptr, nullptr);
}